// round 10
// baseline (speedup 1.0000x reference)
#include <cuda_runtime.h>

// ---------------------------------------------------------------------------
// GCN (3-layer, PyG GCNConv semantics) on GB300.
//   dis = rsqrt(1 + indegree)            (self-loops included)
//   per layer: hs = (A @ W) * dis[row]   (GEMM + fused scale; acc seeded = hs -> self loop)
//              acc[dst] += hs[src]        (edge scatter, RED.ADD.F32)
//              next = relu(dis[row]*acc + b)   (last layer: no relu -> d_out)
//
// edge_index dtype is sniffed at runtime (harness may deliver int64 reference
// data as int32). All decoded indices are clamped to [0, n) so a wrong guess
// produces a measurable rel_err instead of an address-space trap (717).
// ---------------------------------------------------------------------------

#define NMAX 50000
#define EMAX 800000
#define KDIM 256

__device__ float g_deg[NMAX];
__device__ float g_dis[NMAX];
__device__ int   g_src[EMAX];
__device__ int   g_dst[EMAX];
__device__ int   g_i64mode;
__device__ float g_hs [NMAX * KDIM];
__device__ float g_acc[NMAX * KDIM];
__device__ float g_h  [NMAX * KDIM];

// ---------------------------------------------------------------- prep ----
// Detect whether the edge buffer is int64 or int32.
// int64 with values < 2^31: every odd int32 word (hi half) is 0.
// int32: odd words are random node ids, ~all nonzero.
__global__ void sniff_dtype(const int* __restrict__ w, int nwords) {
    if (threadIdx.x == 0 && blockIdx.x == 0) {
        int odd_nz = 0;
        int lim = nwords < 256 ? nwords : 256;
        for (int i = 1; i < lim; i += 2) odd_nz += (w[i] != 0);
        g_i64mode = (odd_nz == 0) ? 1 : 0;
    }
}

__global__ void init_deg(int n) {
    int i = blockIdx.x * blockDim.x + threadIdx.x;
    if (i < n) g_deg[i] = 1.0f;   // self loop contributes 1 to in-degree
}

// Decode edges (either dtype) + degree count in one pass. Indices clamped.
__global__ void prep_edges(const void* __restrict__ ei_raw, int E, int n) {
    int i = blockIdx.x * blockDim.x + threadIdx.x;
    if (i >= E) return;
    int s, d;
    if (g_i64mode) {
        const long long* ei = (const long long*)ei_raw;
        s = (int)ei[i];
        d = (int)ei[E + i];
    } else {
        const int* ei = (const int*)ei_raw;
        s = ei[i];
        d = ei[E + i];
    }
    s = min(max(s, 0), n - 1);
    d = min(max(d, 0), n - 1);
    g_src[i] = s;
    g_dst[i] = d;
    atomicAdd(&g_deg[d], 1.0f);
}

__global__ void calc_dis(int n) {
    int i = blockIdx.x * blockDim.x + threadIdx.x;
    if (i < n) g_dis[i] = rsqrtf(g_deg[i]);   // deg >= 1 always
}

// ---------------------------------------------------------------- GEMM ----
// C[row,col] = (sum_k A[row,k] * W[k,col]) * dis[row]; written to hs AND acc
// (acc seeded with the self-loop term). BM=128, BN=64, BK=16, 256 threads,
// 8x4 outputs per thread.
__global__ __launch_bounds__(256) void sgemm_scaled(
    const float* __restrict__ A, const float* __restrict__ W,
    float* __restrict__ hs, float* __restrict__ acc,
    int n, int Nc)
{
    __shared__ float As[16][132];   // [k][row], padded vs bank conflicts
    __shared__ float Bs[16][64];    // [k][col]

    const int t    = threadIdx.x;
    const int row0 = blockIdx.x * 128;
    const int col0 = blockIdx.y * 64;
    const int tCol = t & 15;    // 16 col-groups * 4 cols
    const int tRow = t >> 4;    // 16 row-groups * 8 rows

    const int ar = t >> 2;           // A tile row (0..63), +64 second half
    const int ak = (t & 3) * 4;      // A k offset (float4)
    const int br = t >> 4;           // B k row (0..15)
    const int bc = (t & 15) * 4;     // B col offset (float4)

    float accr[8][4];
    #pragma unroll
    for (int i = 0; i < 8; i++)
        #pragma unroll
        for (int j = 0; j < 4; j++) accr[i][j] = 0.0f;

    for (int k0 = 0; k0 < KDIM; k0 += 16) {
        #pragma unroll
        for (int half = 0; half < 2; half++) {
            int r = ar + half * 64;
            int grow = row0 + r;
            float4 v = make_float4(0.f, 0.f, 0.f, 0.f);
            if (grow < n) v = *(const float4*)&A[(long)grow * KDIM + k0 + ak];
            As[ak + 0][r] = v.x;
            As[ak + 1][r] = v.y;
            As[ak + 2][r] = v.z;
            As[ak + 3][r] = v.w;
        }
        *(float4*)&Bs[br][bc] = *(const float4*)&W[(k0 + br) * Nc + col0 + bc];
        __syncthreads();

        #pragma unroll
        for (int k = 0; k < 16; k++) {
            float a[8], b[4];
            *(float4*)&a[0] = *(const float4*)&As[k][tRow * 8];
            *(float4*)&a[4] = *(const float4*)&As[k][tRow * 8 + 4];
            *(float4*)&b[0] = *(const float4*)&Bs[k][tCol * 4];
            #pragma unroll
            for (int i = 0; i < 8; i++)
                #pragma unroll
                for (int j = 0; j < 4; j++)
                    accr[i][j] = fmaf(a[i], b[j], accr[i][j]);
        }
        __syncthreads();
    }

    #pragma unroll
    for (int i = 0; i < 8; i++) {
        int row = row0 + tRow * 8 + i;
        if (row < n) {
            float s = g_dis[row];
            float4 v = make_float4(accr[i][0] * s, accr[i][1] * s,
                                   accr[i][2] * s, accr[i][3] * s);
            long off = (long)row * Nc + col0 + tCol * 4;
            *(float4*)&hs[off]  = v;
            *(float4*)&acc[off] = v;   // self-loop term pre-seeded
        }
    }
}

// ------------------------------------------------------------- scatter ----
// One thread per (edge, float4-chunk): acc[dst] += hs[src].
// float4 gather (coalesced within a warp) + 4 scalar atomicAdds (RED.ADD.F32).
template<int LOGC>   // float4-chunks per row = 1<<LOGC (64 for DH=256, 16 for DOUT=64)
__global__ __launch_bounds__(256) void scatter_add(
    const float4* __restrict__ hs, float* __restrict__ acc, int E)
{
    int idx = blockIdx.x * 256 + threadIdx.x;
    int total = E << LOGC;
    if (idx >= total) return;
    int e = idx >> LOGC;
    int c = idx & ((1 << LOGC) - 1);
    int s = g_src[e];
    int d = g_dst[e];
    float4 v = hs[((long)s << LOGC) + c];
    float* p = acc + (((long)d << LOGC) + c) * 4;
    atomicAdd(p + 0, v.x);
    atomicAdd(p + 1, v.y);
    atomicAdd(p + 2, v.z);
    atomicAdd(p + 3, v.w);
}

// ------------------------------------------------------------ epilogue ----
// out = (relu?)( dis[row] * acc + b[col] ), float4-vectorized.
template<int LOG4C, bool RELU>   // Nc/4 = 1<<LOG4C
__global__ __launch_bounds__(256) void pointwise(
    const float4* __restrict__ acc, const float4* __restrict__ b,
    float4* __restrict__ out, int n)
{
    int idx = blockIdx.x * 256 + threadIdx.x;
    int total = n << LOG4C;
    if (idx >= total) return;
    int row  = idx >> LOG4C;
    int col4 = idx & ((1 << LOG4C) - 1);
    float  s  = g_dis[row];
    float4 v  = acc[idx];
    float4 bb = b[col4];
    float4 r;
    r.x = fmaf(s, v.x, bb.x);
    r.y = fmaf(s, v.y, bb.y);
    r.z = fmaf(s, v.z, bb.z);
    r.w = fmaf(s, v.w, bb.w);
    if (RELU) {
        r.x = fmaxf(r.x, 0.f); r.y = fmaxf(r.y, 0.f);
        r.z = fmaxf(r.z, 0.f); r.w = fmaxf(r.w, 0.f);
    }
    out[idx] = r;
}

// -------------------------------------------------------------- launch ----
extern "C" void kernel_launch(void* const* d_in, const int* in_sizes, int n_in,
                              void* d_out, int out_size)
{
    const float* x  = (const float*)d_in[0];
    const void*  ei = d_in[1];               // int64 or int32 — sniffed on device
    const float* W1 = (const float*)d_in[2];
    const float* b1 = (const float*)d_in[3];
    const float* W2 = (const float*)d_in[4];
    const float* b2 = (const float*)d_in[5];
    const float* W3 = (const float*)d_in[6];
    const float* b3 = (const float*)d_in[7];

    const int n = in_sizes[0] / KDIM;   // 50000
    const int E = in_sizes[1] / 2;      // 800000 (element count is dtype-agnostic)

    // Device addresses of scratch (NOT the host shadow symbols).
    float *hs = nullptr, *acc = nullptr, *h = nullptr;
    cudaGetSymbolAddress((void**)&hs,  g_hs);
    cudaGetSymbolAddress((void**)&acc, g_acc);
    cudaGetSymbolAddress((void**)&h,   g_h);

    // --- normalization prep ---
    sniff_dtype<<<1, 32>>>((const int*)ei, 2 * E);
    init_deg  <<<(n + 255) / 256, 256>>>(n);
    prep_edges<<<(E + 255) / 256, 256>>>(ei, E, n);
    calc_dis  <<<(n + 255) / 256, 256>>>(n);

    const dim3 gemm_blk(256);
    const dim3 gemm_grd_h((n + 127) / 128, KDIM / 64);   // Nc = 256
    const dim3 gemm_grd_o((n + 127) / 128, 1);           // Nc = 64

    const int sc_h_blocks = (E * 64 + 255) / 256;
    const int sc_o_blocks = (E * 16 + 255) / 256;
    const int pw_h_blocks = (n * 64 + 255) / 256;        // n*256/4 threads
    const int pw_o_blocks = (n * 16 + 255) / 256;        // n*64/4 threads

    // --- layer 1: x -> h ---
    sgemm_scaled<<<gemm_grd_h, gemm_blk>>>(x, W1, hs, acc, n, KDIM);
    scatter_add<6><<<sc_h_blocks, 256>>>((const float4*)hs, acc, E);
    pointwise<6, true><<<pw_h_blocks, 256>>>((const float4*)acc, (const float4*)b1,
                                             (float4*)h, n);

    // --- layer 2: h -> h ---
    sgemm_scaled<<<gemm_grd_h, gemm_blk>>>(h, W2, hs, acc, n, KDIM);
    scatter_add<6><<<sc_h_blocks, 256>>>((const float4*)hs, acc, E);
    pointwise<6, true><<<pw_h_blocks, 256>>>((const float4*)acc, (const float4*)b2,
                                             (float4*)h, n);

    // --- layer 3: h -> d_out (DOUT=64, no relu) ---
    sgemm_scaled<<<gemm_grd_o, gemm_blk>>>(h, W3, hs, acc, n, 64);
    scatter_add<4><<<sc_o_blocks, 256>>>((const float4*)hs, acc, E);
    pointwise<4, false><<<pw_o_blocks, 256>>>((const float4*)acc, (const float4*)b3,
                                              (float4*)d_out, n);
}

// round 12
// speedup vs baseline: 1.7457x; 1.7457x over previous
#include <cuda_runtime.h>

// ---------------------------------------------------------------------------
// GCN (3-layer, PyG GCNConv semantics) on GB300.
//   dis = rsqrt(1 + indegree)            (self-loops included)
//   per layer: hs = (A @ W) * dis[row]   (GEMM + fused scale; acc seeded = hs -> self loop)
//              acc[dst] += hs[src]        (edge scatter, red.global.add.v4.f32)
//              next = relu(dis[row]*acc + b)   (last layer: no relu -> d_out)
//
// edge_index dtype is sniffed at runtime (harness may deliver int64 reference
// data as int32). All decoded indices are clamped to [0, n) so a wrong guess
// produces a measurable rel_err instead of an address-space trap (717).
// R10 change vs R9-pass: scatter uses vector RED (1 instr / 16B instead of 4
// scalar REDs) — 4x fewer LTS atomic ops.
// ---------------------------------------------------------------------------

#define NMAX 50000
#define EMAX 800000
#define KDIM 256

__device__ float g_deg[NMAX];
__device__ float g_dis[NMAX];
__device__ int   g_src[EMAX];
__device__ int   g_dst[EMAX];
__device__ int   g_i64mode;
__device__ float g_hs [NMAX * KDIM];
__device__ float g_acc[NMAX * KDIM];
__device__ float g_h  [NMAX * KDIM];

// ---------------------------------------------------------------- prep ----
__global__ void sniff_dtype(const int* __restrict__ w, int nwords) {
    if (threadIdx.x == 0 && blockIdx.x == 0) {
        int odd_nz = 0;
        int lim = nwords < 256 ? nwords : 256;
        for (int i = 1; i < lim; i += 2) odd_nz += (w[i] != 0);
        g_i64mode = (odd_nz == 0) ? 1 : 0;
    }
}

__global__ void init_deg(int n) {
    int i = blockIdx.x * blockDim.x + threadIdx.x;
    if (i < n) g_deg[i] = 1.0f;   // self loop contributes 1 to in-degree
}

__global__ void prep_edges(const void* __restrict__ ei_raw, int E, int n) {
    int i = blockIdx.x * blockDim.x + threadIdx.x;
    if (i >= E) return;
    int s, d;
    if (g_i64mode) {
        const long long* ei = (const long long*)ei_raw;
        s = (int)ei[i];
        d = (int)ei[E + i];
    } else {
        const int* ei = (const int*)ei_raw;
        s = ei[i];
        d = ei[E + i];
    }
    s = min(max(s, 0), n - 1);
    d = min(max(d, 0), n - 1);
    g_src[i] = s;
    g_dst[i] = d;
    atomicAdd(&g_deg[d], 1.0f);
}

__global__ void calc_dis(int n) {
    int i = blockIdx.x * blockDim.x + threadIdx.x;
    if (i < n) g_dis[i] = rsqrtf(g_deg[i]);   // deg >= 1 always
}

// ---------------------------------------------------------------- GEMM ----
// C[row,col] = (sum_k A[row,k] * W[k,col]) * dis[row]; written to hs AND acc
// (acc seeded with the self-loop term). BM=128, BN=64, BK=16, 256 threads,
// 8x4 outputs per thread.
__global__ __launch_bounds__(256) void sgemm_scaled(
    const float* __restrict__ A, const float* __restrict__ W,
    float* __restrict__ hs, float* __restrict__ acc,
    int n, int Nc)
{
    __shared__ float As[16][132];   // [k][row], padded vs bank conflicts
    __shared__ float Bs[16][64];    // [k][col]

    const int t    = threadIdx.x;
    const int row0 = blockIdx.x * 128;
    const int col0 = blockIdx.y * 64;
    const int tCol = t & 15;    // 16 col-groups * 4 cols
    const int tRow = t >> 4;    // 16 row-groups * 8 rows

    const int ar = t >> 2;           // A tile row (0..63), +64 second half
    const int ak = (t & 3) * 4;      // A k offset (float4)
    const int br = t >> 4;           // B k row (0..15)
    const int bc = (t & 15) * 4;     // B col offset (float4)

    float accr[8][4];
    #pragma unroll
    for (int i = 0; i < 8; i++)
        #pragma unroll
        for (int j = 0; j < 4; j++) accr[i][j] = 0.0f;

    for (int k0 = 0; k0 < KDIM; k0 += 16) {
        #pragma unroll
        for (int half = 0; half < 2; half++) {
            int r = ar + half * 64;
            int grow = row0 + r;
            float4 v = make_float4(0.f, 0.f, 0.f, 0.f);
            if (grow < n) v = *(const float4*)&A[(long)grow * KDIM + k0 + ak];
            As[ak + 0][r] = v.x;
            As[ak + 1][r] = v.y;
            As[ak + 2][r] = v.z;
            As[ak + 3][r] = v.w;
        }
        *(float4*)&Bs[br][bc] = *(const float4*)&W[(k0 + br) * Nc + col0 + bc];
        __syncthreads();

        #pragma unroll
        for (int k = 0; k < 16; k++) {
            float a[8], b[4];
            *(float4*)&a[0] = *(const float4*)&As[k][tRow * 8];
            *(float4*)&a[4] = *(const float4*)&As[k][tRow * 8 + 4];
            *(float4*)&b[0] = *(const float4*)&Bs[k][tCol * 4];
            #pragma unroll
            for (int i = 0; i < 8; i++)
                #pragma unroll
                for (int j = 0; j < 4; j++)
                    accr[i][j] = fmaf(a[i], b[j], accr[i][j]);
        }
        __syncthreads();
    }

    #pragma unroll
    for (int i = 0; i < 8; i++) {
        int row = row0 + tRow * 8 + i;
        if (row < n) {
            float s = g_dis[row];
            float4 v = make_float4(accr[i][0] * s, accr[i][1] * s,
                                   accr[i][2] * s, accr[i][3] * s);
            long off = (long)row * Nc + col0 + tCol * 4;
            *(float4*)&hs[off]  = v;
            *(float4*)&acc[off] = v;   // self-loop term pre-seeded
        }
    }
}

// ------------------------------------------------------------- scatter ----
// One thread per (edge, float4-chunk): acc[dst] += hs[src].
// float4 gather (coalesced within a warp) + ONE vector RED (16B payload).
template<int LOGC>   // float4-chunks per row = 1<<LOGC (64 for DH=256, 16 for DOUT=64)
__global__ __launch_bounds__(256) void scatter_add(
    const float4* __restrict__ hs, float* __restrict__ acc, int E)
{
    int idx = blockIdx.x * 256 + threadIdx.x;
    int total = E << LOGC;
    if (idx >= total) return;
    int e = idx >> LOGC;
    int c = idx & ((1 << LOGC) - 1);
    int s = g_src[e];
    int d = g_dst[e];
    float4 v = hs[((long)s << LOGC) + c];
    float* p = acc + (((long)d << LOGC) + c) * 4;   // 16B-aligned by construction
    asm volatile("red.global.add.v4.f32 [%0], {%1, %2, %3, %4};"
                 :: "l"(p), "f"(v.x), "f"(v.y), "f"(v.z), "f"(v.w)
                 : "memory");
}

// ------------------------------------------------------------ epilogue ----
// out = (relu?)( dis[row] * acc + b[col] ), float4-vectorized.
template<int LOG4C, bool RELU>   // Nc/4 = 1<<LOG4C
__global__ __launch_bounds__(256) void pointwise(
    const float4* __restrict__ acc, const float4* __restrict__ b,
    float4* __restrict__ out, int n)
{
    int idx = blockIdx.x * 256 + threadIdx.x;
    int total = n << LOG4C;
    if (idx >= total) return;
    int row  = idx >> LOG4C;
    int col4 = idx & ((1 << LOG4C) - 1);
    float  s  = g_dis[row];
    float4 v  = acc[idx];
    float4 bb = b[col4];
    float4 r;
    r.x = fmaf(s, v.x, bb.x);
    r.y = fmaf(s, v.y, bb.y);
    r.z = fmaf(s, v.z, bb.z);
    r.w = fmaf(s, v.w, bb.w);
    if (RELU) {
        r.x = fmaxf(r.x, 0.f); r.y = fmaxf(r.y, 0.f);
        r.z = fmaxf(r.z, 0.f); r.w = fmaxf(r.w, 0.f);
    }
    out[idx] = r;
}

// -------------------------------------------------------------- launch ----
extern "C" void kernel_launch(void* const* d_in, const int* in_sizes, int n_in,
                              void* d_out, int out_size)
{
    const float* x  = (const float*)d_in[0];
    const void*  ei = d_in[1];               // int64 or int32 — sniffed on device
    const float* W1 = (const float*)d_in[2];
    const float* b1 = (const float*)d_in[3];
    const float* W2 = (const float*)d_in[4];
    const float* b2 = (const float*)d_in[5];
    const float* W3 = (const float*)d_in[6];
    const float* b3 = (const float*)d_in[7];

    const int n = in_sizes[0] / KDIM;   // 50000
    const int E = in_sizes[1] / 2;      // 800000

    // Device addresses of scratch (NOT the host shadow symbols).
    float *hs = nullptr, *acc = nullptr, *h = nullptr;
    cudaGetSymbolAddress((void**)&hs,  g_hs);
    cudaGetSymbolAddress((void**)&acc, g_acc);
    cudaGetSymbolAddress((void**)&h,   g_h);

    // --- normalization prep ---
    sniff_dtype<<<1, 32>>>((const int*)ei, 2 * E);
    init_deg  <<<(n + 255) / 256, 256>>>(n);
    prep_edges<<<(E + 255) / 256, 256>>>(ei, E, n);
    calc_dis  <<<(n + 255) / 256, 256>>>(n);

    const dim3 gemm_blk(256);
    const dim3 gemm_grd_h((n + 127) / 128, KDIM / 64);   // Nc = 256
    const dim3 gemm_grd_o((n + 127) / 128, 1);           // Nc = 64

    const int sc_h_blocks = (E * 64 + 255) / 256;
    const int sc_o_blocks = (E * 16 + 255) / 256;
    const int pw_h_blocks = (n * 64 + 255) / 256;        // n*256/4 threads
    const int pw_o_blocks = (n * 16 + 255) / 256;        // n*64/4 threads

    // --- layer 1: x -> h ---
    sgemm_scaled<<<gemm_grd_h, gemm_blk>>>(x, W1, hs, acc, n, KDIM);
    scatter_add<6><<<sc_h_blocks, 256>>>((const float4*)hs, acc, E);
    pointwise<6, true><<<pw_h_blocks, 256>>>((const float4*)acc, (const float4*)b1,
                                             (float4*)h, n);

    // --- layer 2: h -> h ---
    sgemm_scaled<<<gemm_grd_h, gemm_blk>>>(h, W2, hs, acc, n, KDIM);
    scatter_add<6><<<sc_h_blocks, 256>>>((const float4*)hs, acc, E);
    pointwise<6, true><<<pw_h_blocks, 256>>>((const float4*)acc, (const float4*)b2,
                                             (float4*)h, n);

    // --- layer 3: h -> d_out (DOUT=64, no relu) ---
    sgemm_scaled<<<gemm_grd_o, gemm_blk>>>(h, W3, hs, acc, n, 64);
    scatter_add<4><<<sc_o_blocks, 256>>>((const float4*)hs, acc, E);
    pointwise<4, false><<<pw_o_blocks, 256>>>((const float4*)acc, (const float4*)b3,
                                              (float4*)d_out, n);
}